// round 14
// baseline (speedup 1.0000x reference)
#include <cuda_runtime.h>
#include <math.h>
#include <stdint.h>

// Problem dims
#define NB 64
#define NS 64
#define NV 32000
#define NE 768
#define NH 1024
#define NHH 768

#define GRID 128
#define TPB  512

typedef unsigned long long ull;

// ---------------- scratch (device globals; no allocations allowed) ----------
__device__ float g_X    [NB*NS*NE];            // LN'd embeddings, row = s*64+b
__device__ float g_IX   [(size_t)NB*NS*3*NH];  // x_t @ Wi_x + bi, per token
__device__ float g_ILraw[NB*3*NH];             // raw ILOW = IX_t + h_h @ Wi_h
__device__ float g_HG   [NB*3*NH];             // raw h_l @ Wh + bh
__device__ float g_IHI  [NB*3*NHH];            // raw h_l @ hWi + hbi
__device__ float g_HHG  [NB*3*NHH];            // raw h_h @ hWh + hbh
__device__ float2 g_psA [3*64*128];            // partial (sum,sumsq) stats
__device__ float2 g_psB [3*64*128];
__device__ float g_hlT  [NH*64];               // h_l transposed [j][b]
__device__ float g_hhT  [NHH*64];              // h_h transposed [j][b]
__device__ float g_HH   [NB*NS*NHH];           // h_h history, row = t*64+b

// grid barrier state (self-resetting; generation is monotonic across replays)
__device__ unsigned g_bar = 0;
__device__ volatile unsigned g_gen = 0;

// ---------------- f32x2 helpers ---------------------------------------------
__device__ __forceinline__ ull fma2(ull a, ull b, ull c) {
    ull d;
    asm("fma.rn.f32x2 %0, %1, %2, %3;" : "=l"(d) : "l"(a), "l"(b), "l"(c));
    return d;
}
__device__ __forceinline__ ull pk2(float x) {
    ull d;
    asm("mov.b64 %0, {%1, %1};" : "=l"(d) : "f"(x));
    return d;
}
__device__ __forceinline__ void unpk(ull v, float& lo, float& hi) {
    asm("mov.b64 {%0, %1}, %2;" : "=f"(lo), "=f"(hi) : "l"(v));
}
__device__ __forceinline__ void cpa16(unsigned dst, const void* src) {
    asm volatile("cp.async.cg.shared.global [%0], [%1], 16;" :: "r"(dst), "l"(src));
}
__device__ __forceinline__ void cpa4(unsigned dst, const void* src) {
    asm volatile("cp.async.ca.shared.global [%0], [%1], 4;" :: "r"(dst), "l"(src));
}

// ---------------- init: zero hidden states (transposed layouts) -------------
__global__ void k_init() {
    int i = blockIdx.x * 256 + threadIdx.x;
    if (i < NH*64)  g_hlT[i] = 0.f;
    if (i < NHH*64) g_hhT[i] = 0.f;
}

// ---------------- embedding lookup + LayerNorm ------------------------------
__global__ void k_embed(const int* __restrict__ ids, const float* __restrict__ emb,
                        const float* __restrict__ g, const float* __restrict__ bb) {
    int tok = blockIdx.x;            // tok = s*64 + b
    int b = tok & 63, s = tok >> 6;
    int id = ids[b*NS + s];
    const float* e = emb + (size_t)id * NE;
    int tid = threadIdx.x;

    __shared__ float sa[256], sb[256];
    float sum = 0.f, sq = 0.f;
    for (int j = tid; j < NE; j += 256) { float v = e[j]; sum += v; sq += v*v; }
    sa[tid] = sum; sb[tid] = sq; __syncthreads();
    for (int o = 128; o > 0; o >>= 1) {
        if (tid < o) { sa[tid] += sa[tid+o]; sb[tid] += sb[tid+o]; }
        __syncthreads();
    }
    __shared__ float s_m, s_r;
    if (tid == 0) {
        float m = sa[0] / NE;
        float var = sb[0] / NE - m*m;
        s_m = m; s_r = rsqrtf(var + 1e-5f);
    }
    __syncthreads();
    float m = s_m, r = s_r;
    float* xo = g_X + (size_t)tok * NE;
    for (int j = tid; j < NE; j += 256) {
        float v = e[j];
        xo[j] = (v - m) * r * g[j] + bb[j];
    }
}

// ---------------- big GEMM (f32x2): 128x128 tiles ----------------------------
// 256 threads, thread -> 8 rows x 8 cols. Optional output row remap.
__global__ void __launch_bounds__(256) k_gemm_big(
    const float* __restrict__ A, const float* __restrict__ W,
    const float* __restrict__ bias, float* __restrict__ C,
    int K, int N, int remap)
{
    __shared__ __align__(16) float As[32][136];
    __shared__ __align__(16) float Ws[32][136];
    int tid = threadIdx.x;
    int tx = tid & 31, ty = tid >> 5;    // load mapping
    int cx = tid & 15, ry = tid >> 4;    // compute: rows ry*8..+7, cols cx*8..+7
    int n0 = blockIdx.x * 128;
    int m0 = blockIdx.y * 128;

    ull acc[4][8];
    #pragma unroll
    for (int p = 0; p < 4; p++)
        #pragma unroll
        for (int c = 0; c < 8; c++) acc[p][c] = 0ull;

    for (int k0 = 0; k0 < K; k0 += 32) {
        #pragma unroll
        for (int i = 0; i < 16; i++)
            As[tx][ty + 8*i] = A[(size_t)(m0 + ty + 8*i)*K + k0 + tx];
        #pragma unroll
        for (int ii = 0; ii < 4; ii++) {
            int kk = ty*4 + ii;
            #pragma unroll
            for (int jj = 0; jj < 4; jj++)
                Ws[kk][tx + 32*jj] = W[(size_t)(k0 + kk)*N + n0 + tx + 32*jj];
        }
        __syncthreads();
        #pragma unroll
        for (int k = 0; k < 32; k++) {
            ulonglong2 a0 = *reinterpret_cast<const ulonglong2*>(&As[k][ry*8]);
            ulonglong2 a1 = *reinterpret_cast<const ulonglong2*>(&As[k][ry*8 + 4]);
            float4 w0 = *reinterpret_cast<const float4*>(&Ws[k][cx*8]);
            float4 w1 = *reinterpret_cast<const float4*>(&Ws[k][cx*8 + 4]);
            ull wp[8];
            wp[0] = pk2(w0.x); wp[1] = pk2(w0.y); wp[2] = pk2(w0.z); wp[3] = pk2(w0.w);
            wp[4] = pk2(w1.x); wp[5] = pk2(w1.y); wp[6] = pk2(w1.z); wp[7] = pk2(w1.w);
            #pragma unroll
            for (int c = 0; c < 8; c++) {
                acc[0][c] = fma2(a0.x, wp[c], acc[0][c]);
                acc[1][c] = fma2(a0.y, wp[c], acc[1][c]);
                acc[2][c] = fma2(a1.x, wp[c], acc[2][c]);
                acc[3][c] = fma2(a1.y, wp[c], acc[3][c]);
            }
        }
        __syncthreads();
    }
    float bv[8];
    #pragma unroll
    for (int c = 0; c < 8; c++) bv[c] = bias ? bias[n0 + cx*8 + c] : 0.f;
    #pragma unroll
    for (int p = 0; p < 4; p++) {
        int ga = m0 + ry*8 + 2*p, gb = ga + 1;
        size_t ra = remap ? (size_t)((ga & 63)*64 + (ga >> 6)) : (size_t)ga;
        size_t rb = remap ? (size_t)((gb & 63)*64 + (gb >> 6)) : (size_t)gb;
        float oa[8], ob[8];
        #pragma unroll
        for (int c = 0; c < 8; c++) {
            float lo, hi;
            unpk(acc[p][c], lo, hi);
            oa[c] = lo + bv[c];
            ob[c] = hi + bv[c];
        }
        float4* pa = reinterpret_cast<float4*>(C + ra*N + n0 + cx*8);
        float4* pb = reinterpret_cast<float4*>(C + rb*N + n0 + cx*8);
        pa[0] = make_float4(oa[0], oa[1], oa[2], oa[3]);
        pa[1] = make_float4(oa[4], oa[5], oa[6], oa[7]);
        pb[0] = make_float4(ob[0], ob[1], ob[2], ob[3]);
        pb[1] = make_float4(ob[4], ob[5], ob[6], ob[7]);
    }
}

// ================= persistent recurrence kernel ==============================

__device__ __forceinline__ void gridbar() {
    __syncthreads();
    if (threadIdx.x == 0) {
        __threadfence();
        unsigned g = g_gen;
        if (atomicAdd(&g_bar, 1u) == GRID - 1) {
            g_bar = 0;
            __threadfence();
            g_gen = g + 1;
        } else {
            while (g_gen == g) { __nanosleep(64); }
        }
        __threadfence();
    }
    __syncthreads();
}

// Gate-sliced GEMM: block computes cols [g*gw + col0, +8) for each gate g=0..2.
// K split across EIGHT 64-thread groups, f32x2, cp.async double buffering
// (8-k chunks). AT: transposed A [K][64]. Emits per-row/gate (sum,sumsq) of
// this 8-col slice into pst[gate*64*TC + row*TC] (pst pre-offset by tile id).
// sm (floats): [0,8192)     A: eighth e at e*1024 (2 bufs x 512 = 8k x 64);
//              [8192,12288) W: eighth e at 8192+e*512 (2 bufs x 256 = [8k][8cc][4],
//                              slot = k*32 + cc*4 + g; the 4th float is pad).
// W smem loads are one LDS.128 per k (3 gate values), conflict-free.
// Epilogue: two-stage reduction in sm[0,6144) (4 regions x 1536).
__device__ __forceinline__ void gemmG(
    const float* __restrict__ AT, int K,
    const float* __restrict__ W, int N, int gw, int col0,
    const float* __restrict__ bias, const float* __restrict__ Add,
    float* __restrict__ C, float2* __restrict__ pst, int TC,
    float* __restrict__ sm)
{
    int tid = threadIdx.x;
    int er = tid >> 6;                   // K-eighth 0..7
    int lt = tid & 63;
    int rg = lt >> 3;                    // rowgroup 0..7 (rows rg*8..+7)
    int cc = lt & 7;                     // col within 8-wide gate slice
    int Ke = K >> 3;
    int nc = Ke >> 3;                    // 8-k chunks
    const float* ATe = AT + (size_t)er * Ke * 64;
    float* Abase = sm + er * 1024;
    float* Wbase = sm + 8192 + er * 512;
    unsigned smA = (unsigned)__cvta_generic_to_shared(Abase);
    unsigned smW = (unsigned)__cvta_generic_to_shared(Wbase);

    // W 4B-gather descriptors: 3 items/thread; item i in [0,192):
    //   kk = i/24, rem = i%24, g = rem>>3, c2 = rem&7
    //   src = W[(er*Ke + kk)*N + g*gw + col0 + c2], dst slot = kk*32 + c2*4 + g
    const float* wsrc[3];
    unsigned wdst[3];
    #pragma unroll
    for (int r = 0; r < 3; r++) {
        int i = lt + 64*r;
        int kk = i / 24;
        int rem = i - kk*24;
        int gg = rem >> 3, c2 = rem & 7;
        wsrc[r] = W + (size_t)(er*Ke + kk)*N + (size_t)gg*gw + col0 + c2;
        wdst[r] = smW + (unsigned)(kk*32 + c2*4 + gg)*4;
    }

    ull acc[3][4];
    #pragma unroll
    for (int g = 0; g < 3; g++)
        #pragma unroll
        for (int j = 0; j < 4; j++) acc[g][j] = 0ull;

    // prefetch chunk 0: A 512 floats (2x16B/thr), W 192 4B items (3/thr)
    cpa16(smA + lt*16,        ATe + (size_t)lt*4);
    cpa16(smA + (lt + 64)*16, ATe + (size_t)(lt + 64)*4);
    cpa4(wdst[0], wsrc[0]);
    cpa4(wdst[1], wsrc[1]);
    cpa4(wdst[2], wsrc[2]);
    asm volatile("cp.async.commit_group;");

    for (int ch = 0; ch < nc; ch++) {
        if (ch + 1 < nc) {
            int bs = (ch + 1) & 1;
            const float* aseg = ATe + (size_t)(ch + 1) * 8 * 64;
            cpa16(smA + bs*2048 + lt*16,        aseg + (size_t)lt*4);
            cpa16(smA + bs*2048 + (lt + 64)*16, aseg + (size_t)(lt + 64)*4);
            cpa4(wdst[0] + bs*1024, wsrc[0] + 8*N);
            cpa4(wdst[1] + bs*1024, wsrc[1] + 8*N);
            cpa4(wdst[2] + bs*1024, wsrc[2] + 8*N);
            wsrc[0] += 8*N; wsrc[1] += 8*N; wsrc[2] += 8*N;
            asm volatile("cp.async.commit_group;");
            asm volatile("cp.async.wait_group 1;");
        } else {
            asm volatile("cp.async.wait_group 0;");
        }
        asm volatile("bar.sync %0, 64;" :: "r"(er + 1) : "memory");
        const float* As  = Abase + (ch & 1)*512;
        const float* Wsb = Wbase + (ch & 1)*256;
        #pragma unroll
        for (int k = 0; k < 8; k++) {
            ulonglong2 aA = *reinterpret_cast<const ulonglong2*>(As + k*64 + rg*8);
            ulonglong2 aB = *reinterpret_cast<const ulonglong2*>(As + k*64 + rg*8 + 4);
            float4 wv = *reinterpret_cast<const float4*>(Wsb + k*32 + cc*4);
            ull w0 = pk2(wv.x), w1 = pk2(wv.y), w2 = pk2(wv.z);
            acc[0][0] = fma2(aA.x, w0, acc[0][0]);
            acc[0][1] = fma2(aA.y, w0, acc[0][1]);
            acc[0][2] = fma2(aB.x, w0, acc[0][2]);
            acc[0][3] = fma2(aB.y, w0, acc[0][3]);
            acc[1][0] = fma2(aA.x, w1, acc[1][0]);
            acc[1][1] = fma2(aA.y, w1, acc[1][1]);
            acc[1][2] = fma2(aB.x, w1, acc[1][2]);
            acc[1][3] = fma2(aB.y, w1, acc[1][3]);
            acc[2][0] = fma2(aA.x, w2, acc[2][0]);
            acc[2][1] = fma2(aA.y, w2, acc[2][1]);
            acc[2][2] = fma2(aB.x, w2, acc[2][2]);
            acc[2][3] = fma2(aB.y, w2, acc[2][3]);
        }
        asm volatile("bar.sync %0, 64;" :: "r"(er + 1) : "memory");
    }

    // unpack partials
    float o[3][8];
    #pragma unroll
    for (int g = 0; g < 3; g++) {
        unpk(acc[g][0], o[g][0], o[g][1]);
        unpk(acc[g][1], o[g][2], o[g][3]);
        unpk(acc[g][2], o[g][4], o[g][5]);
        unpk(acc[g][3], o[g][6], o[g][7]);
    }

    // two-stage reduction: regions r=0..3 of 1536 floats at sm[r*1536]
    __syncthreads();                       // all eighths done with A/W buffers
    if (er >= 4) {
        float* R = sm + (er - 4)*1536;
        #pragma unroll
        for (int g = 0; g < 3; g++)
            #pragma unroll
            for (int i = 0; i < 8; i++)
                R[(rg*8 + i)*24 + g*8 + cc] = o[g][i];
    }
    __syncthreads();
    if (er < 4) {
        float* R = sm + er*1536;
        #pragma unroll
        for (int g = 0; g < 3; g++)
            #pragma unroll
            for (int i = 0; i < 8; i++)
                R[(rg*8 + i)*24 + g*8 + cc] += o[g][i];
    }
    __syncthreads();

    // final: 192 threads, one (gate,row) each: sum 4 regions over 8 cols,
    // +bias/+Add, store, emit LN slice stats (no shuffles).
    if (tid < 192) {
        int gate = tid >> 6, row = tid & 63;
        int base = row*24 + gate*8;
        float4 v0 = make_float4(0.f, 0.f, 0.f, 0.f);
        float4 v1 = make_float4(0.f, 0.f, 0.f, 0.f);
        #pragma unroll
        for (int r = 0; r < 4; r++) {
            float4 p0 = *reinterpret_cast<const float4*>(sm + r*1536 + base);
            float4 p1 = *reinterpret_cast<const float4*>(sm + r*1536 + base + 4);
            v0.x += p0.x; v0.y += p0.y; v0.z += p0.z; v0.w += p0.w;
            v1.x += p1.x; v1.y += p1.y; v1.z += p1.z; v1.w += p1.w;
        }
        size_t cix = (size_t)gate*gw + col0;
        if (bias) {
            float4 b0 = *reinterpret_cast<const float4*>(bias + cix);
            float4 b1 = *reinterpret_cast<const float4*>(bias + cix + 4);
            v0.x += b0.x; v0.y += b0.y; v0.z += b0.z; v0.w += b0.w;
            v1.x += b1.x; v1.y += b1.y; v1.z += b1.z; v1.w += b1.w;
        }
        if (Add) {
            float4 a0 = *reinterpret_cast<const float4*>(Add + (size_t)row*N + cix);
            float4 a1 = *reinterpret_cast<const float4*>(Add + (size_t)row*N + cix + 4);
            v0.x += a0.x; v0.y += a0.y; v0.z += a0.z; v0.w += a0.w;
            v1.x += a1.x; v1.y += a1.y; v1.z += a1.z; v1.w += a1.w;
        }
        *reinterpret_cast<float4*>(C + (size_t)row*N + cix)     = v0;
        *reinterpret_cast<float4*>(C + (size_t)row*N + cix + 4) = v1;
        float s = v0.x + v0.y + v0.z + v0.w + v1.x + v1.y + v1.z + v1.w;
        float qq = v0.x*v0.x + v0.y*v0.y + v0.z*v0.z + v0.w*v0.w
                 + v1.x*v1.x + v1.y*v1.y + v1.z*v1.z + v1.w*v1.w;
        pst[(size_t)gate*64*TC + row*TC] = make_float2(s, qq);
    }
    __syncthreads();
}

// warp-cooperative stats finalize: sum TC partials, return (mean, rstd)
__device__ __forceinline__ float2 warp_stat(const float2* __restrict__ p, int TC, float inv_hid) {
    int l = threadIdx.x & 31;
    float s = 0.f, q = 0.f;
    #pragma unroll
    for (int i = 0; i < 4; i++) {
        if (l + 32*i < TC) { s += p[l + 32*i].x; q += p[l + 32*i].y; }
    }
    #pragma unroll
    for (int o = 16; o > 0; o >>= 1) {
        s += __shfl_xor_sync(0xffffffffu, s, o);
        q += __shfl_xor_sync(0xffffffffu, q, o);
    }
    float m = s * inv_hid;
    float r = rsqrtf(q * inv_hid - m*m + 1e-5f);
    return make_float2(m, r);
}

__device__ __forceinline__ float sigm(float x) { return 1.f / (1.f + expf(-x)); }

__global__ void __launch_bounds__(TPB, 1) k_recur(
    const float* __restrict__ lWi, const float* __restrict__ lbh,
    const float* __restrict__ lWh,
    const float* __restrict__ llig, const float* __restrict__ llib,
    const float* __restrict__ llhg, const float* __restrict__ llhb,
    const float* __restrict__ hWi,  const float* __restrict__ hbi,
    const float* __restrict__ hWh,  const float* __restrict__ hbh,
    const float* __restrict__ hlig, const float* __restrict__ hlib,
    const float* __restrict__ hlhg, const float* __restrict__ hlhb)
{
    __shared__ __align__(16) float sm[12288];   // 48 KB exactly
    float* s_st = sm + 8192;                    // aliases W region (dead in combines)

    const float* lWi_h = lWi + (size_t)NE * 3 * NH;  // rows 768..1535 of low_Wi
    int bid = blockIdx.x, tid = threadIdx.x;
    int w = tid >> 5;
    int b = bid & 63, half = bid >> 6;
    int col0 = bid * 8;

    for (int t = 0; t < NS; t++) {
        const float* ixt = g_IX + (size_t)t * NB * 3 * NH;
        for (int c = 0; c < 3; c++) {
            // ---- phase A: HG(u=0) + ILOW (both depend only on current state)
            gemmG(g_hlT, NH, lWh, 3*NH, NH, col0, lbh, nullptr,
                  g_HG, g_psB + bid, 128, sm);
            gemmG(g_hhT, NHH, lWi_h, 3*NH, NH, col0, nullptr, ixt,
                  g_ILraw, g_psA + bid, 128, sm);
            gridbar();

            // ---- low-cell inner loop ----------------------------------------
            for (int u = 0; u < 5; u++) {
                // combine: LN(IL) + LN(HG) + gates -> h_lT
                if (w < 6) {
                    const float2* p = (w < 3)
                        ? g_psA + (size_t)w*64*128 + b*128
                        : g_psB + (size_t)(w-3)*64*128 + b*128;
                    float2 mr = warp_stat(p, 128, 1.f/NH);
                    if ((tid & 31) == 0) { s_st[2*w] = mr.x; s_st[2*w+1] = mr.y; }
                }
                __syncthreads();
                {
                    const float* Ib = g_ILraw + (size_t)b*3*NH;
                    const float* Hb = g_HG    + (size_t)b*3*NH;
                    int j = half*512 + tid;   // 512 threads cover the 512-slice
                    float i0 = (Ib[j       ] - s_st[0])*s_st[1]*llig[j       ] + llib[j       ];
                    float i1 = (Ib[NH  + j ] - s_st[2])*s_st[3]*llig[NH  + j ] + llib[NH  + j ];
                    float i2 = (Ib[2*NH + j] - s_st[4])*s_st[5]*llig[2*NH + j] + llib[2*NH + j];
                    float h0 = (Hb[j       ] - s_st[6])*s_st[7]*llhg[j       ] + llhb[j       ];
                    float h1 = (Hb[NH  + j ] - s_st[8])*s_st[9]*llhg[NH  + j ] + llhb[NH  + j ];
                    float h2 = (Hb[2*NH + j] - s_st[10])*s_st[11]*llhg[2*NH + j] + llhb[2*NH + j];
                    float r = sigm(i0 + h0);
                    float z = sigm(i1 + h1);
                    float n = tanhf(i2 + r*h2);
                    float hp = g_hlT[(size_t)j*64 + b];
                    g_hlT[(size_t)j*64 + b] = (1.f - z)*n + z*hp;
                }
                gridbar();
                if (u < 4) {
                    gemmG(g_hlT, NH, lWh, 3*NH, NH, col0, lbh, nullptr,
                          g_HG, g_psB + bid, 128, sm);
                    gridbar();
                }
            }

            // ---- high-cell GEMMs: 96 blocks, 8-col gate slices --------------
            if (bid < 96) {
                gemmG(g_hlT, NH, hWi, 3*NHH, NHH, col0, hbi, nullptr,
                      g_IHI, g_psA + bid, 96, sm);
                gemmG(g_hhT, NHH, hWh, 3*NHH, NHH, col0, hbh, nullptr,
                      g_HHG, g_psB + bid, 96, sm);
            }
            gridbar();

            // ---- high combine -> h_hT (+history at c==2) --------------------
            if (w < 6) {
                const float2* p = (w < 3)
                    ? g_psA + (size_t)w*64*96 + b*96
                    : g_psB + (size_t)(w-3)*64*96 + b*96;
                float2 mr = warp_stat(p, 96, 1.f/NHH);
                if ((tid & 31) == 0) { s_st[2*w] = mr.x; s_st[2*w+1] = mr.y; }
            }
            __syncthreads();
            if (tid < 384) {
                const float* Ib = g_IHI + (size_t)b*3*NHH;
                const float* Hb = g_HHG + (size_t)b*3*NHH;
                int j = half*384 + tid;
                float i0 = (Ib[j        ] - s_st[0])*s_st[1]*hlig[j        ] + hlib[j        ];
                float i1 = (Ib[NHH  + j ] - s_st[2])*s_st[3]*hlig[NHH  + j ] + hlib[NHH  + j ];
                float i2 = (Ib[2*NHH + j] - s_st[4])*s_st[5]*hlig[2*NHH + j] + hlib[2*NHH + j];
                float h0 = (Hb[j        ] - s_st[6])*s_st[7]*hlhg[j        ] + hlhb[j        ];
                float h1 = (Hb[NHH  + j ] - s_st[8])*s_st[9]*hlhg[NHH  + j ] + hlhb[NHH  + j ];
                float h2 = (Hb[2*NHH + j] - s_st[10])*s_st[11]*hlhg[2*NHH + j] + hlhb[2*NHH + j];
                float r = sigm(i0 + h0);
                float z = sigm(i1 + h1);
                float n = tanhf(i2 + r*h2);
                float hp = g_hhT[(size_t)j*64 + b];
                float nv = (1.f - z)*n + z*hp;
                g_hhT[(size_t)j*64 + b] = nv;
                if (c == 2) g_HH[(size_t)(t*64 + b)*NHH + j] = nv;
            }
            gridbar();
        }
    }
}

// ---------------- host orchestration ----------------------------------------
extern "C" void kernel_launch(void* const* d_in, const int* in_sizes, int n_in,
                              void* d_out, int out_size) {
    const int*   ids  = (const int*)  d_in[0];
    const float* emb  = (const float*)d_in[1];
    const float* leg  = (const float*)d_in[2];
    const float* leb  = (const float*)d_in[3];
    const float* lWi  = (const float*)d_in[4];   // [1536, 3072]
    const float* lbi  = (const float*)d_in[5];
    const float* lWh  = (const float*)d_in[6];   // [1024, 3072]
    const float* lbh  = (const float*)d_in[7];
    const float* llig = (const float*)d_in[8];
    const float* llib = (const float*)d_in[9];
    const float* llhg = (const float*)d_in[10];
    const float* llhb = (const float*)d_in[11];
    const float* hWi  = (const float*)d_in[12];  // [1024, 2304]
    const float* hbi  = (const float*)d_in[13];
    const float* hWh  = (const float*)d_in[14];  // [768, 2304]
    const float* hbh  = (const float*)d_in[15];
    const float* hlig = (const float*)d_in[16];
    const float* hlib = (const float*)d_in[17];
    const float* hlhg = (const float*)d_in[18];
    const float* hlhb = (const float*)d_in[19];
    const float* Wout = (const float*)d_in[20];  // [768, 32000]
    const float* bout = (const float*)d_in[21];
    float* out = (float*)d_out;

    float *pX, *pIX, *pHH;
    cudaGetSymbolAddress((void**)&pX,  g_X);
    cudaGetSymbolAddress((void**)&pIX, g_IX);
    cudaGetSymbolAddress((void**)&pHH, g_HH);

    // zero hidden states (transposed layouts)
    k_init<<<256, 256>>>();

    // x = LN(emb[ids]) laid out [S, B, E]
    k_embed<<<NB*NS, 256>>>(ids, emb, leg, leb);

    // IX = x @ Wi_x + bi for ALL tokens up front (reused 15x per step)
    k_gemm_big<<<dim3((3*NH)/128, (NB*NS)/128), 256>>>(pX, lWi, lbi, pIX, NE, 3*NH, 0);

    // full recurrence in ONE persistent kernel (software grid barriers)
    k_recur<<<GRID, TPB>>>(lWi, lbh, lWh,
                           llig, llib, llhg, llhb,
                           hWi, hbi, hWh, hbh,
                           hlig, hlib, hlhg, hlhb);

    // logits = h_h_hist @ Wout + bout, row remap (s*64+b) -> out[(b*64+s)*V]
    k_gemm_big<<<dim3(NV/128, (NB*NS)/128), 256>>>(pHH, Wout, bout, out, NHH, NV, 1);
}

// round 15
// speedup vs baseline: 1.0250x; 1.0250x over previous
#include <cuda_runtime.h>
#include <math.h>
#include <stdint.h>

// Problem dims
#define NB 64
#define NS 64
#define NV 32000
#define NE 768
#define NH 1024
#define NHH 768

#define GRID 128
#define TPB  512

typedef unsigned long long ull;

// ---------------- scratch (device globals; no allocations allowed) ----------
__device__ float g_X    [NB*NS*NE];            // LN'd embeddings, row = s*64+b
__device__ float g_IX   [(size_t)NB*NS*3*NH];  // x_t @ Wi_x + bi, per token
__device__ float g_ILraw[NB*3*NH];             // raw ILOW = IX_t + h_h @ Wi_h
__device__ float g_HG   [NB*3*NH];             // raw h_l @ Wh + bh
__device__ float g_IHI  [NB*3*NHH];            // raw h_l @ hWi + hbi
__device__ float g_HHG  [NB*3*NHH];            // raw h_h @ hWh + hbh
__device__ float2 g_psA [3*64*128];            // partial (sum,sumsq) stats
__device__ float2 g_psB [3*64*128];
__device__ float g_hlT  [NH*64];               // h_l transposed [j][b]
__device__ float g_hhT  [NHH*64];              // h_h transposed [j][b]
__device__ float g_HH   [NB*NS*NHH];           // h_h history, row = t*64+b

// two-level grid barrier (monotonic counters; no resets; replay-safe)
__device__ unsigned g_barc[8];
__device__ unsigned g_bar = 0;
__device__ volatile unsigned g_gen = 0;

// ---------------- f32x2 helpers ---------------------------------------------
__device__ __forceinline__ ull fma2(ull a, ull b, ull c) {
    ull d;
    asm("fma.rn.f32x2 %0, %1, %2, %3;" : "=l"(d) : "l"(a), "l"(b), "l"(c));
    return d;
}
__device__ __forceinline__ ull pk2(float x) {
    ull d;
    asm("mov.b64 %0, {%1, %1};" : "=l"(d) : "f"(x));
    return d;
}
__device__ __forceinline__ void unpk(ull v, float& lo, float& hi) {
    asm("mov.b64 {%0, %1}, %2;" : "=f"(lo), "=f"(hi) : "l"(v));
}
__device__ __forceinline__ void cpa16(unsigned dst, const void* src) {
    asm volatile("cp.async.cg.shared.global [%0], [%1], 16;" :: "r"(dst), "l"(src));
}

// ---------------- init: zero hidden states (transposed layouts) -------------
__global__ void k_init() {
    int i = blockIdx.x * 256 + threadIdx.x;
    if (i < NH*64)  g_hlT[i] = 0.f;
    if (i < NHH*64) g_hhT[i] = 0.f;
}

// ---------------- embedding lookup + LayerNorm ------------------------------
__global__ void k_embed(const int* __restrict__ ids, const float* __restrict__ emb,
                        const float* __restrict__ g, const float* __restrict__ bb) {
    int tok = blockIdx.x;            // tok = s*64 + b
    int b = tok & 63, s = tok >> 6;
    int id = ids[b*NS + s];
    const float* e = emb + (size_t)id * NE;
    int tid = threadIdx.x;

    __shared__ float sa[256], sb[256];
    float sum = 0.f, sq = 0.f;
    for (int j = tid; j < NE; j += 256) { float v = e[j]; sum += v; sq += v*v; }
    sa[tid] = sum; sb[tid] = sq; __syncthreads();
    for (int o = 128; o > 0; o >>= 1) {
        if (tid < o) { sa[tid] += sa[tid+o]; sb[tid] += sb[tid+o]; }
        __syncthreads();
    }
    __shared__ float s_m, s_r;
    if (tid == 0) {
        float m = sa[0] / NE;
        float var = sb[0] / NE - m*m;
        s_m = m; s_r = rsqrtf(var + 1e-5f);
    }
    __syncthreads();
    float m = s_m, r = s_r;
    float* xo = g_X + (size_t)tok * NE;
    for (int j = tid; j < NE; j += 256) {
        float v = e[j];
        xo[j] = (v - m) * r * g[j] + bb[j];
    }
}

// ---------------- big GEMM (f32x2): 128x128 tiles ----------------------------
// 256 threads, thread -> 8 rows x 8 cols. Optional output row remap.
__global__ void __launch_bounds__(256) k_gemm_big(
    const float* __restrict__ A, const float* __restrict__ W,
    const float* __restrict__ bias, float* __restrict__ C,
    int K, int N, int remap)
{
    __shared__ __align__(16) float As[32][136];
    __shared__ __align__(16) float Ws[32][136];
    int tid = threadIdx.x;
    int tx = tid & 31, ty = tid >> 5;    // load mapping
    int cx = tid & 15, ry = tid >> 4;    // compute: rows ry*8..+7, cols cx*8..+7
    int n0 = blockIdx.x * 128;
    int m0 = blockIdx.y * 128;

    ull acc[4][8];
    #pragma unroll
    for (int p = 0; p < 4; p++)
        #pragma unroll
        for (int c = 0; c < 8; c++) acc[p][c] = 0ull;

    for (int k0 = 0; k0 < K; k0 += 32) {
        #pragma unroll
        for (int i = 0; i < 16; i++)
            As[tx][ty + 8*i] = A[(size_t)(m0 + ty + 8*i)*K + k0 + tx];
        #pragma unroll
        for (int ii = 0; ii < 4; ii++) {
            int kk = ty*4 + ii;
            #pragma unroll
            for (int jj = 0; jj < 4; jj++)
                Ws[kk][tx + 32*jj] = W[(size_t)(k0 + kk)*N + n0 + tx + 32*jj];
        }
        __syncthreads();
        #pragma unroll
        for (int k = 0; k < 32; k++) {
            ulonglong2 a0 = *reinterpret_cast<const ulonglong2*>(&As[k][ry*8]);
            ulonglong2 a1 = *reinterpret_cast<const ulonglong2*>(&As[k][ry*8 + 4]);
            float4 w0 = *reinterpret_cast<const float4*>(&Ws[k][cx*8]);
            float4 w1 = *reinterpret_cast<const float4*>(&Ws[k][cx*8 + 4]);
            ull wp[8];
            wp[0] = pk2(w0.x); wp[1] = pk2(w0.y); wp[2] = pk2(w0.z); wp[3] = pk2(w0.w);
            wp[4] = pk2(w1.x); wp[5] = pk2(w1.y); wp[6] = pk2(w1.z); wp[7] = pk2(w1.w);
            #pragma unroll
            for (int c = 0; c < 8; c++) {
                acc[0][c] = fma2(a0.x, wp[c], acc[0][c]);
                acc[1][c] = fma2(a0.y, wp[c], acc[1][c]);
                acc[2][c] = fma2(a1.x, wp[c], acc[2][c]);
                acc[3][c] = fma2(a1.y, wp[c], acc[3][c]);
            }
        }
        __syncthreads();
    }
    float bv[8];
    #pragma unroll
    for (int c = 0; c < 8; c++) bv[c] = bias ? bias[n0 + cx*8 + c] : 0.f;
    #pragma unroll
    for (int p = 0; p < 4; p++) {
        int ga = m0 + ry*8 + 2*p, gb = ga + 1;
        size_t ra = remap ? (size_t)((ga & 63)*64 + (ga >> 6)) : (size_t)ga;
        size_t rb = remap ? (size_t)((gb & 63)*64 + (gb >> 6)) : (size_t)gb;
        float oa[8], ob[8];
        #pragma unroll
        for (int c = 0; c < 8; c++) {
            float lo, hi;
            unpk(acc[p][c], lo, hi);
            oa[c] = lo + bv[c];
            ob[c] = hi + bv[c];
        }
        float4* pa = reinterpret_cast<float4*>(C + ra*N + n0 + cx*8);
        float4* pb = reinterpret_cast<float4*>(C + rb*N + n0 + cx*8);
        pa[0] = make_float4(oa[0], oa[1], oa[2], oa[3]);
        pa[1] = make_float4(oa[4], oa[5], oa[6], oa[7]);
        pb[0] = make_float4(ob[0], ob[1], ob[2], ob[3]);
        pb[1] = make_float4(ob[4], ob[5], ob[6], ob[7]);
    }
}

// ================= persistent recurrence kernel ==============================

// Two-level barrier: 8 sub-counters (16 blocks each) -> master (8 leaders).
// Monotonic counters; completion targets derived from the generation value,
// so no resets are needed and state is consistent across graph replays.
__device__ __forceinline__ void gridbar() {
    __syncthreads();
    if (threadIdx.x == 0) {
        __threadfence();
        unsigned g = g_gen;
        unsigned pos = atomicAdd(&g_barc[blockIdx.x & 7], 1u);
        if (pos == 16u*g + 15u) {
            unsigned m = atomicAdd(&g_bar, 1u);
            if (m == 8u*g + 7u) {
                __threadfence();
                g_gen = g + 1;
            }
        }
        while (g_gen == g) { __nanosleep(32); }
        __threadfence();
    }
    __syncthreads();
}

// Gate-sliced GEMM: block computes cols [g*gw + col0, +8) for each gate g=0..2.
// K split across EIGHT 64-thread groups, f32x2, cp.async double buffering
// (8-k chunks). AT: transposed A [K][64]. Emits per-row/gate (sum,sumsq) of
// this 8-col slice into pst[gate*64*TC + row*TC] (pst pre-offset by tile id).
// sm (floats): [0,8192)  A: eighth e at e*1024 (2 bufs x 512 = 8k x 64);
//              [8192,11264) W: eighth e at 8192+e*384 (2 bufs x 192 = 8k x 24).
// Epilogue: two-stage reduction in sm[0,6144) (4 regions x 1536).
__device__ __forceinline__ void gemmG(
    const float* __restrict__ AT, int K,
    const float* __restrict__ W, int N, int gw, int col0,
    const float* __restrict__ bias, const float* __restrict__ Add,
    float* __restrict__ C, float2* __restrict__ pst, int TC,
    float* __restrict__ sm)
{
    int tid = threadIdx.x;
    int er = tid >> 6;                   // K-eighth 0..7
    int lt = tid & 63;
    int rg = lt >> 3;                    // rowgroup 0..7 (rows rg*8..+7)
    int cc = lt & 7;                     // col within 8-wide gate slice
    int Ke = K >> 3;
    int nc = Ke >> 3;                    // 8-k chunks
    const float* ATe = AT + (size_t)er * Ke * 64;
    float* Abase = sm + er * 1024;
    float* Wbase = sm + 8192 + er * 384;
    unsigned smA = (unsigned)__cvta_generic_to_shared(Abase);
    unsigned smW = (unsigned)__cvta_generic_to_shared(Wbase);

    // W transfer: 48 x 16B per chunk (8k x 3 gates x 2 4-float parts)
    int kkw = lt / 6, rw = lt - 6*kkw;   // gate = rw>>1, part = rw&1
    const float* wsrc = W + (size_t)(er*Ke + kkw)*N + (rw >> 1)*gw + col0 + (rw & 1)*4;
    unsigned wdst = smW + (unsigned)(kkw*24 + (rw >> 1)*8 + (rw & 1)*4)*4;
    bool wdo = lt < 48;

    ull acc[3][4];
    #pragma unroll
    for (int g = 0; g < 3; g++)
        #pragma unroll
        for (int j = 0; j < 4; j++) acc[g][j] = 0ull;

    // prefetch chunk 0: A 512 floats (2x16B/thr), W 192 floats
    cpa16(smA + lt*16,        ATe + (size_t)lt*4);
    cpa16(smA + (lt + 64)*16, ATe + (size_t)(lt + 64)*4);
    if (wdo) cpa16(wdst, wsrc);
    asm volatile("cp.async.commit_group;");

    for (int ch = 0; ch < nc; ch++) {
        if (ch + 1 < nc) {
            int bs = (ch + 1) & 1;
            const float* aseg = ATe + (size_t)(ch + 1) * 8 * 64;
            cpa16(smA + bs*2048 + lt*16,        aseg + (size_t)lt*4);
            cpa16(smA + bs*2048 + (lt + 64)*16, aseg + (size_t)(lt + 64)*4);
            if (wdo) cpa16(wdst + bs*768, wsrc + 8*N);
            wsrc += 8*N;
            asm volatile("cp.async.commit_group;");
            asm volatile("cp.async.wait_group 1;");
        } else {
            asm volatile("cp.async.wait_group 0;");
        }
        asm volatile("bar.sync %0, 64;" :: "r"(er + 1) : "memory");
        const float* As  = Abase + (ch & 1)*512;
        const float* Wsb = Wbase + (ch & 1)*192;
        #pragma unroll
        for (int k = 0; k < 8; k++) {
            ulonglong2 aA = *reinterpret_cast<const ulonglong2*>(As + k*64 + rg*8);
            ulonglong2 aB = *reinterpret_cast<const ulonglong2*>(As + k*64 + rg*8 + 4);
            #pragma unroll
            for (int g = 0; g < 3; g++) {
                ull w = pk2(Wsb[k*24 + g*8 + cc]);
                acc[g][0] = fma2(aA.x, w, acc[g][0]);
                acc[g][1] = fma2(aA.y, w, acc[g][1]);
                acc[g][2] = fma2(aB.x, w, acc[g][2]);
                acc[g][3] = fma2(aB.y, w, acc[g][3]);
            }
        }
        asm volatile("bar.sync %0, 64;" :: "r"(er + 1) : "memory");
    }

    // unpack partials
    float o[3][8];
    #pragma unroll
    for (int g = 0; g < 3; g++) {
        unpk(acc[g][0], o[g][0], o[g][1]);
        unpk(acc[g][1], o[g][2], o[g][3]);
        unpk(acc[g][2], o[g][4], o[g][5]);
        unpk(acc[g][3], o[g][6], o[g][7]);
    }

    // two-stage reduction: regions r=0..3 of 1536 floats at sm[r*1536]
    __syncthreads();                       // all eighths done with A/W buffers
    if (er >= 4) {
        float* R = sm + (er - 4)*1536;
        #pragma unroll
        for (int g = 0; g < 3; g++)
            #pragma unroll
            for (int i = 0; i < 8; i++)
                R[(rg*8 + i)*24 + g*8 + cc] = o[g][i];
    }
    __syncthreads();
    if (er < 4) {
        float* R = sm + er*1536;
        #pragma unroll
        for (int g = 0; g < 3; g++)
            #pragma unroll
            for (int i = 0; i < 8; i++)
                R[(rg*8 + i)*24 + g*8 + cc] += o[g][i];
    }
    __syncthreads();

    // final: 192 threads, one (gate,row) each: sum 4 regions over 8 cols,
    // +bias/+Add, store, emit LN slice stats (no shuffles).
    if (tid < 192) {
        int gate = tid >> 6, row = tid & 63;
        int base = row*24 + gate*8;
        float4 v0 = make_float4(0.f, 0.f, 0.f, 0.f);
        float4 v1 = make_float4(0.f, 0.f, 0.f, 0.f);
        #pragma unroll
        for (int r = 0; r < 4; r++) {
            float4 p0 = *reinterpret_cast<const float4*>(sm + r*1536 + base);
            float4 p1 = *reinterpret_cast<const float4*>(sm + r*1536 + base + 4);
            v0.x += p0.x; v0.y += p0.y; v0.z += p0.z; v0.w += p0.w;
            v1.x += p1.x; v1.y += p1.y; v1.z += p1.z; v1.w += p1.w;
        }
        size_t cix = (size_t)gate*gw + col0;
        if (bias) {
            float4 b0 = *reinterpret_cast<const float4*>(bias + cix);
            float4 b1 = *reinterpret_cast<const float4*>(bias + cix + 4);
            v0.x += b0.x; v0.y += b0.y; v0.z += b0.z; v0.w += b0.w;
            v1.x += b1.x; v1.y += b1.y; v1.z += b1.z; v1.w += b1.w;
        }
        if (Add) {
            float4 a0 = *reinterpret_cast<const float4*>(Add + (size_t)row*N + cix);
            float4 a1 = *reinterpret_cast<const float4*>(Add + (size_t)row*N + cix + 4);
            v0.x += a0.x; v0.y += a0.y; v0.z += a0.z; v0.w += a0.w;
            v1.x += a1.x; v1.y += a1.y; v1.z += a1.z; v1.w += a1.w;
        }
        *reinterpret_cast<float4*>(C + (size_t)row*N + cix)     = v0;
        *reinterpret_cast<float4*>(C + (size_t)row*N + cix + 4) = v1;
        float s = v0.x + v0.y + v0.z + v0.w + v1.x + v1.y + v1.z + v1.w;
        float qq = v0.x*v0.x + v0.y*v0.y + v0.z*v0.z + v0.w*v0.w
                 + v1.x*v1.x + v1.y*v1.y + v1.z*v1.z + v1.w*v1.w;
        pst[(size_t)gate*64*TC + row*TC] = make_float2(s, qq);
    }
    __syncthreads();
}

// warp-cooperative stats finalize: sum TC partials, return (mean, rstd)
__device__ __forceinline__ float2 warp_stat(const float2* __restrict__ p, int TC, float inv_hid) {
    int l = threadIdx.x & 31;
    float s = 0.f, q = 0.f;
    #pragma unroll
    for (int i = 0; i < 4; i++) {
        if (l + 32*i < TC) { s += p[l + 32*i].x; q += p[l + 32*i].y; }
    }
    #pragma unroll
    for (int o = 16; o > 0; o >>= 1) {
        s += __shfl_xor_sync(0xffffffffu, s, o);
        q += __shfl_xor_sync(0xffffffffu, q, o);
    }
    float m = s * inv_hid;
    float r = rsqrtf(q * inv_hid - m*m + 1e-5f);
    return make_float2(m, r);
}

__device__ __forceinline__ float sigm(float x) { return 1.f / (1.f + expf(-x)); }

__global__ void __launch_bounds__(TPB, 1) k_recur(
    const float* __restrict__ lWi, const float* __restrict__ lbh,
    const float* __restrict__ lWh,
    const float* __restrict__ llig, const float* __restrict__ llib,
    const float* __restrict__ llhg, const float* __restrict__ llhb,
    const float* __restrict__ hWi,  const float* __restrict__ hbi,
    const float* __restrict__ hWh,  const float* __restrict__ hbh,
    const float* __restrict__ hlig, const float* __restrict__ hlib,
    const float* __restrict__ hlhg, const float* __restrict__ hlhb)
{
    __shared__ __align__(16) float sm[11264];
    __shared__ float s_st[12];

    const float* lWi_h = lWi + (size_t)NE * 3 * NH;  // rows 768..1535 of low_Wi
    int bid = blockIdx.x, tid = threadIdx.x;
    int w = tid >> 5;
    int b = bid & 63, half = bid >> 6;
    int col0 = bid * 8;

    for (int t = 0; t < NS; t++) {
        const float* ixt = g_IX + (size_t)t * NB * 3 * NH;
        for (int c = 0; c < 3; c++) {
            // ---- phase A: HG(u=0) + ILOW (both depend only on current state)
            gemmG(g_hlT, NH, lWh, 3*NH, NH, col0, lbh, nullptr,
                  g_HG, g_psB + bid, 128, sm);
            gemmG(g_hhT, NHH, lWi_h, 3*NH, NH, col0, nullptr, ixt,
                  g_ILraw, g_psA + bid, 128, sm);
            gridbar();

            // ---- low-cell inner loop ----------------------------------------
            for (int u = 0; u < 5; u++) {
                // combine: LN(IL) + LN(HG) + gates -> h_lT
                if (w < 6) {
                    const float2* p = (w < 3)
                        ? g_psA + (size_t)w*64*128 + b*128
                        : g_psB + (size_t)(w-3)*64*128 + b*128;
                    float2 mr = warp_stat(p, 128, 1.f/NH);
                    if ((tid & 31) == 0) { s_st[2*w] = mr.x; s_st[2*w+1] = mr.y; }
                }
                __syncthreads();
                {
                    const float* Ib = g_ILraw + (size_t)b*3*NH;
                    const float* Hb = g_HG    + (size_t)b*3*NH;
                    int j = half*512 + tid;   // 512 threads cover the 512-slice
                    float i0 = (Ib[j       ] - s_st[0])*s_st[1]*llig[j       ] + llib[j       ];
                    float i1 = (Ib[NH  + j ] - s_st[2])*s_st[3]*llig[NH  + j ] + llib[NH  + j ];
                    float i2 = (Ib[2*NH + j] - s_st[4])*s_st[5]*llig[2*NH + j] + llib[2*NH + j];
                    float h0 = (Hb[j       ] - s_st[6])*s_st[7]*llhg[j       ] + llhb[j       ];
                    float h1 = (Hb[NH  + j ] - s_st[8])*s_st[9]*llhg[NH  + j ] + llhb[NH  + j ];
                    float h2 = (Hb[2*NH + j] - s_st[10])*s_st[11]*llhg[2*NH + j] + llhb[2*NH + j];
                    float r = sigm(i0 + h0);
                    float z = sigm(i1 + h1);
                    float n = tanhf(i2 + r*h2);
                    float hp = g_hlT[(size_t)j*64 + b];
                    g_hlT[(size_t)j*64 + b] = (1.f - z)*n + z*hp;
                }
                gridbar();
                if (u < 4) {
                    gemmG(g_hlT, NH, lWh, 3*NH, NH, col0, lbh, nullptr,
                          g_HG, g_psB + bid, 128, sm);
                    gridbar();
                }
            }

            // ---- high-cell GEMMs: 96 blocks, 8-col gate slices --------------
            if (bid < 96) {
                gemmG(g_hlT, NH, hWi, 3*NHH, NHH, col0, hbi, nullptr,
                      g_IHI, g_psA + bid, 96, sm);
                gemmG(g_hhT, NHH, hWh, 3*NHH, NHH, col0, hbh, nullptr,
                      g_HHG, g_psB + bid, 96, sm);
            }
            gridbar();

            // ---- high combine -> h_hT (+history at c==2) --------------------
            if (w < 6) {
                const float2* p = (w < 3)
                    ? g_psA + (size_t)w*64*96 + b*96
                    : g_psB + (size_t)(w-3)*64*96 + b*96;
                float2 mr = warp_stat(p, 96, 1.f/NHH);
                if ((tid & 31) == 0) { s_st[2*w] = mr.x; s_st[2*w+1] = mr.y; }
            }
            __syncthreads();
            if (tid < 384) {
                const float* Ib = g_IHI + (size_t)b*3*NHH;
                const float* Hb = g_HHG + (size_t)b*3*NHH;
                int j = half*384 + tid;
                float i0 = (Ib[j        ] - s_st[0])*s_st[1]*hlig[j        ] + hlib[j        ];
                float i1 = (Ib[NHH  + j ] - s_st[2])*s_st[3]*hlig[NHH  + j ] + hlib[NHH  + j ];
                float i2 = (Ib[2*NHH + j] - s_st[4])*s_st[5]*hlig[2*NHH + j] + hlib[2*NHH + j];
                float h0 = (Hb[j        ] - s_st[6])*s_st[7]*hlhg[j        ] + hlhb[j        ];
                float h1 = (Hb[NHH  + j ] - s_st[8])*s_st[9]*hlhg[NHH  + j ] + hlhb[NHH  + j ];
                float h2 = (Hb[2*NHH + j] - s_st[10])*s_st[11]*hlhg[2*NHH + j] + hlhb[2*NHH + j];
                float r = sigm(i0 + h0);
                float z = sigm(i1 + h1);
                float n = tanhf(i2 + r*h2);
                float hp = g_hhT[(size_t)j*64 + b];
                float nv = (1.f - z)*n + z*hp;
                g_hhT[(size_t)j*64 + b] = nv;
                if (c == 2) g_HH[(size_t)(t*64 + b)*NHH + j] = nv;
            }
            gridbar();
        }
    }
}

// ---------------- host orchestration ----------------------------------------
extern "C" void kernel_launch(void* const* d_in, const int* in_sizes, int n_in,
                              void* d_out, int out_size) {
    const int*   ids  = (const int*)  d_in[0];
    const float* emb  = (const float*)d_in[1];
    const float* leg  = (const float*)d_in[2];
    const float* leb  = (const float*)d_in[3];
    const float* lWi  = (const float*)d_in[4];   // [1536, 3072]
    const float* lbi  = (const float*)d_in[5];
    const float* lWh  = (const float*)d_in[6];   // [1024, 3072]
    const float* lbh  = (const float*)d_in[7];
    const float* llig = (const float*)d_in[8];
    const float* llib = (const float*)d_in[9];
    const float* llhg = (const float*)d_in[10];
    const float* llhb = (const float*)d_in[11];
    const float* hWi  = (const float*)d_in[12];  // [1024, 2304]
    const float* hbi  = (const float*)d_in[13];
    const float* hWh  = (const float*)d_in[14];  // [768, 2304]
    const float* hbh  = (const float*)d_in[15];
    const float* hlig = (const float*)d_in[16];
    const float* hlib = (const float*)d_in[17];
    const float* hlhg = (const float*)d_in[18];
    const float* hlhb = (const float*)d_in[19];
    const float* Wout = (const float*)d_in[20];  // [768, 32000]
    const float* bout = (const float*)d_in[21];
    float* out = (float*)d_out;

    float *pX, *pIX, *pHH;
    cudaGetSymbolAddress((void**)&pX,  g_X);
    cudaGetSymbolAddress((void**)&pIX, g_IX);
    cudaGetSymbolAddress((void**)&pHH, g_HH);

    // zero hidden states (transposed layouts)
    k_init<<<256, 256>>>();

    // x = LN(emb[ids]) laid out [S, B, E]
    k_embed<<<NB*NS, 256>>>(ids, emb, leg, leb);

    // IX = x @ Wi_x + bi for ALL tokens up front (reused 15x per step)
    k_gemm_big<<<dim3((3*NH)/128, (NB*NS)/128), 256>>>(pX, lWi, lbi, pIX, NE, 3*NH, 0);

    // full recurrence in ONE persistent kernel (software grid barriers)
    k_recur<<<GRID, TPB>>>(lWi, lbh, lWh,
                           llig, llib, llhg, llhb,
                           hWi, hbi, hWh, hbh,
                           hlig, hlib, hlhg, hlhb);

    // logits = h_h_hist @ Wout + bout, row remap (s*64+b) -> out[(b*64+s)*V]
    k_gemm_big<<<dim3(NV/128, (NB*NS)/128), 256>>>(pHH, Wout, bout, out, NHH, NV, 1);
}

// round 16
// speedup vs baseline: 1.3226x; 1.2904x over previous
#include <cuda_runtime.h>
#include <cuda_bf16.h>
#include <math.h>
#include <stdint.h>

// Problem dims
#define NB 64
#define NS 64
#define NV 32000
#define NE 768
#define NH 1024
#define NHH 768

#define GRID 128
#define TPB  512

typedef unsigned long long ull;
typedef __nv_bfloat16 bf16;

// ---------------- scratch (device globals; no allocations allowed) ----------
__device__ float g_X    [NB*NS*NE];
__device__ float g_IX   [(size_t)NB*NS*3*NH];
__device__ float g_ILraw[NB*3*NH];
__device__ float g_HG   [NB*3*NH];
__device__ float g_IHI  [NB*3*NHH];
__device__ float g_HHG  [NB*3*NHH];
__device__ float2 g_psA [3*64*128];
__device__ float2 g_psB [3*64*128];
__device__ float g_hlT  [NH*64];               // h_l fp32 state [j][b]
__device__ float g_hhT  [NHH*64];              // h_h fp32 state [j][b]
__device__ float g_HH   [NB*NS*NHH];           // h_h history

// bf16 split images of the states (A operands), layout [k][64]
__device__ bf16 g_lAh[NH*64],  g_lAl[NH*64];
__device__ bf16 g_hAh[NHH*64], g_hAl[NHH*64];

// bf16 split weights (B operands), layout [k][3N] like the fp32 originals
__device__ bf16 g_Wlh_h[(size_t)NH*3*NH],   g_Wlh_l[(size_t)NH*3*NH];
__device__ bf16 g_Wlx_h[(size_t)NHH*3*NH],  g_Wlx_l[(size_t)NHH*3*NH];
__device__ bf16 g_Wih_h[(size_t)NH*3*NHH],  g_Wih_l[(size_t)NH*3*NHH];
__device__ bf16 g_Whh_h[(size_t)NHH*3*NHH], g_Whh_l[(size_t)NHH*3*NHH];

// two-level grid barrier (monotonic; replay-safe)
__device__ unsigned g_barc[8];
__device__ unsigned g_bar = 0;
__device__ volatile unsigned g_gen = 0;

// ---------------- helpers -----------------------------------------------------
__device__ __forceinline__ ull fma2(ull a, ull b, ull c) {
    ull d;
    asm("fma.rn.f32x2 %0, %1, %2, %3;" : "=l"(d) : "l"(a), "l"(b), "l"(c));
    return d;
}
__device__ __forceinline__ ull pk2(float x) {
    ull d; asm("mov.b64 %0, {%1, %1};" : "=l"(d) : "f"(x)); return d;
}
__device__ __forceinline__ void unpk(ull v, float& lo, float& hi) {
    asm("mov.b64 {%0, %1}, %2;" : "=f"(lo), "=f"(hi) : "l"(v));
}
__device__ __forceinline__ void cpa16(unsigned dst, const void* src) {
    asm volatile("cp.async.cg.shared.global [%0], [%1], 16;" :: "r"(dst), "l"(src));
}
__device__ __forceinline__ void ldsm4t(uint32_t* r, unsigned a) {
    asm volatile("ldmatrix.sync.aligned.m8n8.x4.trans.shared.b16 {%0,%1,%2,%3},[%4];"
        : "=r"(r[0]), "=r"(r[1]), "=r"(r[2]), "=r"(r[3]) : "r"(a));
}
__device__ __forceinline__ void ldsm2t(uint32_t* r, unsigned a) {
    asm volatile("ldmatrix.sync.aligned.m8n8.x2.trans.shared.b16 {%0,%1},[%2];"
        : "=r"(r[0]), "=r"(r[1]) : "r"(a));
}
__device__ __forceinline__ void mmabf(float* d, const uint32_t* a, const uint32_t* b) {
    asm volatile("mma.sync.aligned.m16n8k16.row.col.f32.bf16.bf16.f32 "
        "{%0,%1,%2,%3},{%4,%5,%6,%7},{%8,%9},{%0,%1,%2,%3};"
        : "+f"(d[0]), "+f"(d[1]), "+f"(d[2]), "+f"(d[3])
        : "r"(a[0]), "r"(a[1]), "r"(a[2]), "r"(a[3]), "r"(b[0]), "r"(b[1]));
}

// ---------------- init: zero states + bf16 images -----------------------------
__global__ void k_init() {
    int i = blockIdx.x * 256 + threadIdx.x;
    if (i < NH*64)  { g_hlT[i] = 0.f; g_lAh[i] = __float2bfloat16(0.f); g_lAl[i] = __float2bfloat16(0.f); }
    if (i < NHH*64) { g_hhT[i] = 0.f; g_hAh[i] = __float2bfloat16(0.f); g_hAl[i] = __float2bfloat16(0.f); }
}

// ---------------- weight split conversion -------------------------------------
__global__ void k_cvt(const float* __restrict__ src, bf16* __restrict__ hi,
                      bf16* __restrict__ lo, int n) {
    int i = blockIdx.x * 512 + threadIdx.x;
    if (i < n) {
        float v = src[i];
        bf16 h = __float2bfloat16(v);
        hi[i] = h;
        lo[i] = __float2bfloat16(v - __bfloat162float(h));
    }
}

// ---------------- embedding lookup + LayerNorm --------------------------------
__global__ void k_embed(const int* __restrict__ ids, const float* __restrict__ emb,
                        const float* __restrict__ g, const float* __restrict__ bb) {
    int tok = blockIdx.x;
    int b = tok & 63, s = tok >> 6;
    int id = ids[b*NS + s];
    const float* e = emb + (size_t)id * NE;
    int tid = threadIdx.x;

    __shared__ float sa[256], sb[256];
    float sum = 0.f, sq = 0.f;
    for (int j = tid; j < NE; j += 256) { float v = e[j]; sum += v; sq += v*v; }
    sa[tid] = sum; sb[tid] = sq; __syncthreads();
    for (int o = 128; o > 0; o >>= 1) {
        if (tid < o) { sa[tid] += sa[tid+o]; sb[tid] += sb[tid+o]; }
        __syncthreads();
    }
    __shared__ float s_m, s_r;
    if (tid == 0) {
        float m = sa[0] / NE;
        float var = sb[0] / NE - m*m;
        s_m = m; s_r = rsqrtf(var + 1e-5f);
    }
    __syncthreads();
    float m = s_m, r = s_r;
    float* xo = g_X + (size_t)tok * NE;
    for (int j = tid; j < NE; j += 256) {
        float v = e[j];
        xo[j] = (v - m) * r * g[j] + bb[j];
    }
}

// ---------------- big GEMM (f32x2): 128x128 tiles (IX + logits) ----------------
__global__ void __launch_bounds__(256) k_gemm_big(
    const float* __restrict__ A, const float* __restrict__ W,
    const float* __restrict__ bias, float* __restrict__ C,
    int K, int N, int remap)
{
    __shared__ __align__(16) float As[32][136];
    __shared__ __align__(16) float Ws[32][136];
    int tid = threadIdx.x;
    int tx = tid & 31, ty = tid >> 5;
    int cx = tid & 15, ry = tid >> 4;
    int n0 = blockIdx.x * 128;
    int m0 = blockIdx.y * 128;

    ull acc[4][8];
    #pragma unroll
    for (int p = 0; p < 4; p++)
        #pragma unroll
        for (int c = 0; c < 8; c++) acc[p][c] = 0ull;

    for (int k0 = 0; k0 < K; k0 += 32) {
        #pragma unroll
        for (int i = 0; i < 16; i++)
            As[tx][ty + 8*i] = A[(size_t)(m0 + ty + 8*i)*K + k0 + tx];
        #pragma unroll
        for (int ii = 0; ii < 4; ii++) {
            int kk = ty*4 + ii;
            #pragma unroll
            for (int jj = 0; jj < 4; jj++)
                Ws[kk][tx + 32*jj] = W[(size_t)(k0 + kk)*N + n0 + tx + 32*jj];
        }
        __syncthreads();
        #pragma unroll
        for (int k = 0; k < 32; k++) {
            ulonglong2 a0 = *reinterpret_cast<const ulonglong2*>(&As[k][ry*8]);
            ulonglong2 a1 = *reinterpret_cast<const ulonglong2*>(&As[k][ry*8 + 4]);
            float4 w0 = *reinterpret_cast<const float4*>(&Ws[k][cx*8]);
            float4 w1 = *reinterpret_cast<const float4*>(&Ws[k][cx*8 + 4]);
            ull wp[8];
            wp[0] = pk2(w0.x); wp[1] = pk2(w0.y); wp[2] = pk2(w0.z); wp[3] = pk2(w0.w);
            wp[4] = pk2(w1.x); wp[5] = pk2(w1.y); wp[6] = pk2(w1.z); wp[7] = pk2(w1.w);
            #pragma unroll
            for (int c = 0; c < 8; c++) {
                acc[0][c] = fma2(a0.x, wp[c], acc[0][c]);
                acc[1][c] = fma2(a0.y, wp[c], acc[1][c]);
                acc[2][c] = fma2(a1.x, wp[c], acc[2][c]);
                acc[3][c] = fma2(a1.y, wp[c], acc[3][c]);
            }
        }
        __syncthreads();
    }
    float bv[8];
    #pragma unroll
    for (int c = 0; c < 8; c++) bv[c] = bias ? bias[n0 + cx*8 + c] : 0.f;
    #pragma unroll
    for (int p = 0; p < 4; p++) {
        int ga = m0 + ry*8 + 2*p, gb = ga + 1;
        size_t ra = remap ? (size_t)((ga & 63)*64 + (ga >> 6)) : (size_t)ga;
        size_t rb = remap ? (size_t)((gb & 63)*64 + (gb >> 6)) : (size_t)gb;
        float oa[8], ob[8];
        #pragma unroll
        for (int c = 0; c < 8; c++) {
            float lo, hi;
            unpk(acc[p][c], lo, hi);
            oa[c] = lo + bv[c];
            ob[c] = hi + bv[c];
        }
        float4* pa = reinterpret_cast<float4*>(C + ra*N + n0 + cx*8);
        float4* pb = reinterpret_cast<float4*>(C + rb*N + n0 + cx*8);
        pa[0] = make_float4(oa[0], oa[1], oa[2], oa[3]);
        pa[1] = make_float4(oa[4], oa[5], oa[6], oa[7]);
        pb[0] = make_float4(ob[0], ob[1], ob[2], ob[3]);
        pb[1] = make_float4(ob[4], ob[5], ob[6], ob[7]);
    }
}

// ================= persistent recurrence kernel ================================

__device__ __forceinline__ void gridbar() {
    __syncthreads();
    if (threadIdx.x == 0) {
        __threadfence();
        unsigned g = g_gen;
        unsigned pos = atomicAdd(&g_barc[blockIdx.x & 7], 1u);
        if (pos == 16u*g + 15u) {
            unsigned m = atomicAdd(&g_bar, 1u);
            if (m == 8u*g + 7u) {
                __threadfence();
                g_gen = g + 1;
            }
        }
        while (g_gen == g) { __nanosleep(32); }
        __threadfence();
    }
    __syncthreads();
}

// Tensor-core gate-sliced GEMM (split-bf16, 3-term). Block computes cols
// [g*gw + col0, +8) per gate. 4 K-quarters x 4 warps; warp = m16 x 3 n8 tiles.
// A images [k][64] bf16 (hi/lo), SW128-swizzled into smem; W bf16 [k][Nw].
// sm bytes: [0,32768) A: quarter q at q*8192, buf bs at +bs*4096 (hi 2048 | lo 2048)
//           [32768,45056) W: quarter q at 32768+q*3072, buf bs at +bs*1536 (hi 768 | lo 768)
// Epilogue: 2 regions x 1536 floats aliased at sm[0).
__device__ __forceinline__ void gemmM(
    const bf16* __restrict__ Ah, const bf16* __restrict__ Al, int K,
    const bf16* __restrict__ Wh, const bf16* __restrict__ Wl,
    int Nw, int gw, int col0,
    const float* __restrict__ bias, const float* __restrict__ Add,
    float* __restrict__ C, float2* __restrict__ pst, int TC,
    char* __restrict__ sm)
{
    int tid = threadIdx.x;
    int qr = tid >> 7, lt = tid & 127;
    int wq = lt >> 5, lane = tid & 31;
    int Kq = K >> 2, nch = Kq >> 4;
    int gk0 = qr * Kq;
    unsigned sb = (unsigned)__cvta_generic_to_shared(sm);
    unsigned Aq = sb + qr*8192;
    unsigned Wq = sb + 32768 + qr*3072;

    // cp.async descriptors (A: 128 x 16B per term; W: 48 x 16B per term)
    int kkA = lt >> 3, blkA = lt & 7;
    unsigned dstA = Aq + (unsigned)(kkA*128 + ((blkA ^ (kkA & 7)) * 16));
    const bf16* pAh = Ah + (size_t)(gk0 + kkA)*64 + blkA*8;
    const bf16* pAl = Al + (size_t)(gk0 + kkA)*64 + blkA*8;

    bool wHi = lt < 48, wLo = (lt >= 64 && lt < 112);
    int wi = wHi ? lt : (lt - 64);
    int kkW = wi / 3, pW = wi - 3*kkW;
    unsigned dstW = Wq + (wLo ? 768u : 0u) + (unsigned)(kkW*48 + pW*16);
    const bf16* pWsrc = (wHi ? Wh : Wl) + (size_t)(gk0 + kkW)*Nw + (size_t)pW*gw + col0;
    bool wDo = wHi || wLo;

    // ldmatrix lane offsets
    int m0 = wq * 16;
    int mi = lane >> 3, lr = lane & 7;
    int kA = lr + (mi >> 1)*8;
    int mc = m0 + (mi & 1)*8;
    unsigned offA = (unsigned)(kA*128 + (((mc >> 3) ^ (kA & 7)) * 16));
    unsigned offW = (unsigned)((lane & 15) * 48);

    float d[3][4];
    #pragma unroll
    for (int nt = 0; nt < 3; nt++)
        #pragma unroll
        for (int j = 0; j < 4; j++) d[nt][j] = 0.f;

    // prefetch chunk 0
    cpa16(dstA,        pAh);
    cpa16(dstA + 2048, pAl);
    if (wDo) cpa16(dstW, pWsrc);
    asm volatile("cp.async.commit_group;");

    for (int ch = 0; ch < nch; ch++) {
        if (ch + 1 < nch) {
            int bs = (ch + 1) & 1;
            pAh += 16*64; pAl += 16*64; pWsrc += (size_t)16*Nw;
            cpa16(dstA + bs*4096,        pAh);
            cpa16(dstA + bs*4096 + 2048, pAl);
            if (wDo) cpa16(dstW + bs*1536, pWsrc);
            asm volatile("cp.async.commit_group;");
            asm volatile("cp.async.wait_group 1;");
        } else {
            asm volatile("cp.async.wait_group 0;");
        }
        asm volatile("bar.sync %0, 128;" :: "r"(qr + 1) : "memory");
        unsigned Ab = Aq + (ch & 1)*4096;
        unsigned Wb = Wq + (ch & 1)*1536;
        uint32_t ah[4], al[4];
        ldsm4t(ah, Ab + offA);
        ldsm4t(al, Ab + 2048 + offA);
        #pragma unroll
        for (int nt = 0; nt < 3; nt++) {
            uint32_t bh[2], bl[2];
            ldsm2t(bh, Wb + offW + nt*16);
            ldsm2t(bl, Wb + 768 + offW + nt*16);
            mmabf(d[nt], ah, bh);
            mmabf(d[nt], ah, bl);
            mmabf(d[nt], al, bh);
        }
        asm volatile("bar.sync %0, 128;" :: "r"(qr + 1) : "memory");
    }

    // ---- 2-stage reduction across quarters (regions 0,1 of 1536 floats) ----
    __syncthreads();
    float* Rw = (float*)sm;
    {
        int r = lane >> 2, c2 = (lane & 3) * 2;
        if (qr >= 2) {
            float* R = Rw + (qr - 2) * 1536;
            #pragma unroll
            for (int nt = 0; nt < 3; nt++) {
                R[(m0 + r)*24 + nt*8 + c2]         = d[nt][0];
                R[(m0 + r)*24 + nt*8 + c2 + 1]     = d[nt][1];
                R[(m0 + r + 8)*24 + nt*8 + c2]     = d[nt][2];
                R[(m0 + r + 8)*24 + nt*8 + c2 + 1] = d[nt][3];
            }
        }
        __syncthreads();
        if (qr < 2) {
            float* R = Rw + qr * 1536;
            #pragma unroll
            for (int nt = 0; nt < 3; nt++) {
                R[(m0 + r)*24 + nt*8 + c2]         += d[nt][0];
                R[(m0 + r)*24 + nt*8 + c2 + 1]     += d[nt][1];
                R[(m0 + r + 8)*24 + nt*8 + c2]     += d[nt][2];
                R[(m0 + r + 8)*24 + nt*8 + c2 + 1] += d[nt][3];
            }
        }
    }
    __syncthreads();

    // final: 192 threads, one (gate,row): sum 2 regions, +bias/+Add, store, stats
    if (tid < 192) {
        int gate = tid >> 6, row = tid & 63;
        int base = row*24 + gate*8;
        float4 p0 = *reinterpret_cast<const float4*>(Rw + base);
        float4 p1 = *reinterpret_cast<const float4*>(Rw + base + 4);
        float4 q0 = *reinterpret_cast<const float4*>(Rw + 1536 + base);
        float4 q1 = *reinterpret_cast<const float4*>(Rw + 1536 + base + 4);
        float4 v0 = make_float4(p0.x+q0.x, p0.y+q0.y, p0.z+q0.z, p0.w+q0.w);
        float4 v1 = make_float4(p1.x+q1.x, p1.y+q1.y, p1.z+q1.z, p1.w+q1.w);
        size_t cix = (size_t)gate*gw + col0;
        if (bias) {
            float4 b0 = *reinterpret_cast<const float4*>(bias + cix);
            float4 b1 = *reinterpret_cast<const float4*>(bias + cix + 4);
            v0.x += b0.x; v0.y += b0.y; v0.z += b0.z; v0.w += b0.w;
            v1.x += b1.x; v1.y += b1.y; v1.z += b1.z; v1.w += b1.w;
        }
        if (Add) {
            float4 a0 = *reinterpret_cast<const float4*>(Add + (size_t)row*Nw + cix);
            float4 a1 = *reinterpret_cast<const float4*>(Add + (size_t)row*Nw + cix + 4);
            v0.x += a0.x; v0.y += a0.y; v0.z += a0.z; v0.w += a0.w;
            v1.x += a1.x; v1.y += a1.y; v1.z += a1.z; v1.w += a1.w;
        }
        *reinterpret_cast<float4*>(C + (size_t)row*Nw + cix)     = v0;
        *reinterpret_cast<float4*>(C + (size_t)row*Nw + cix + 4) = v1;
        float s = v0.x + v0.y + v0.z + v0.w + v1.x + v1.y + v1.z + v1.w;
        float qq = v0.x*v0.x + v0.y*v0.y + v0.z*v0.z + v0.w*v0.w
                 + v1.x*v1.x + v1.y*v1.y + v1.z*v1.z + v1.w*v1.w;
        pst[(size_t)gate*64*TC + row*TC] = make_float2(s, qq);
    }
    __syncthreads();
}

// warp-cooperative stats finalize
__device__ __forceinline__ float2 warp_stat(const float2* __restrict__ p, int TC, float inv_hid) {
    int l = threadIdx.x & 31;
    float s = 0.f, q = 0.f;
    #pragma unroll
    for (int i = 0; i < 4; i++) {
        if (l + 32*i < TC) { s += p[l + 32*i].x; q += p[l + 32*i].y; }
    }
    #pragma unroll
    for (int o = 16; o > 0; o >>= 1) {
        s += __shfl_xor_sync(0xffffffffu, s, o);
        q += __shfl_xor_sync(0xffffffffu, q, o);
    }
    float m = s * inv_hid;
    float r = rsqrtf(q * inv_hid - m*m + 1e-5f);
    return make_float2(m, r);
}

__device__ __forceinline__ float sigm(float x) { return 1.f / (1.f + expf(-x)); }

__global__ void __launch_bounds__(TPB, 1) k_recur(
    const float* __restrict__ lbh,
    const float* __restrict__ llig, const float* __restrict__ llib,
    const float* __restrict__ llhg, const float* __restrict__ llhb,
    const float* __restrict__ hbi,  const float* __restrict__ hbh,
    const float* __restrict__ hlig, const float* __restrict__ hlib,
    const float* __restrict__ hlhg, const float* __restrict__ hlhb)
{
    __shared__ __align__(16) char sm[45056];
    __shared__ float s_st[12];

    int bid = blockIdx.x, tid = threadIdx.x;
    int w = tid >> 5;
    int b = bid & 63, half = bid >> 6;
    int col0 = bid * 8;

    for (int t = 0; t < NS; t++) {
        const float* ixt = g_IX + (size_t)t * NB * 3 * NH;
        for (int c = 0; c < 3; c++) {
            // ---- phase A: HG(u=0) + ILOW ------------------------------------
            gemmM(g_lAh, g_lAl, NH,  g_Wlh_h, g_Wlh_l, 3*NH, NH, col0,
                  lbh, nullptr, g_HG, g_psB + bid, 128, sm);
            gemmM(g_hAh, g_hAl, NHH, g_Wlx_h, g_Wlx_l, 3*NH, NH, col0,
                  nullptr, ixt, g_ILraw, g_psA + bid, 128, sm);
            gridbar();

            // ---- low-cell inner loop ----------------------------------------
            for (int u = 0; u < 5; u++) {
                if (w < 6) {
                    const float2* p = (w < 3)
                        ? g_psA + (size_t)w*64*128 + b*128
                        : g_psB + (size_t)(w-3)*64*128 + b*128;
                    float2 mr = warp_stat(p, 128, 1.f/NH);
                    if ((tid & 31) == 0) { s_st[2*w] = mr.x; s_st[2*w+1] = mr.y; }
                }
                __syncthreads();
                {
                    const float* Ib = g_ILraw + (size_t)b*3*NH;
                    const float* Hb = g_HG    + (size_t)b*3*NH;
                    int j = half*512 + tid;
                    float i0 = (Ib[j       ] - s_st[0])*s_st[1]*llig[j       ] + llib[j       ];
                    float i1 = (Ib[NH  + j ] - s_st[2])*s_st[3]*llig[NH  + j ] + llib[NH  + j ];
                    float i2 = (Ib[2*NH + j] - s_st[4])*s_st[5]*llig[2*NH + j] + llib[2*NH + j];
                    float h0 = (Hb[j       ] - s_st[6])*s_st[7]*llhg[j       ] + llhb[j       ];
                    float h1 = (Hb[NH  + j ] - s_st[8])*s_st[9]*llhg[NH  + j ] + llhb[NH  + j ];
                    float h2 = (Hb[2*NH + j] - s_st[10])*s_st[11]*llhg[2*NH + j] + llhb[2*NH + j];
                    float r = sigm(i0 + h0);
                    float z = sigm(i1 + h1);
                    float n = tanhf(i2 + r*h2);
                    float hp = g_hlT[(size_t)j*64 + b];
                    float nv = (1.f - z)*n + z*hp;
                    g_hlT[(size_t)j*64 + b] = nv;
                    bf16 hh16 = __float2bfloat16(nv);
                    g_lAh[(size_t)j*64 + b] = hh16;
                    g_lAl[(size_t)j*64 + b] = __float2bfloat16(nv - __bfloat162float(hh16));
                }
                gridbar();
                if (u < 4) {
                    gemmM(g_lAh, g_lAl, NH, g_Wlh_h, g_Wlh_l, 3*NH, NH, col0,
                          lbh, nullptr, g_HG, g_psB + bid, 128, sm);
                    gridbar();
                }
            }

            // ---- high-cell GEMMs (96 blocks) --------------------------------
            if (bid < 96) {
                gemmM(g_lAh, g_lAl, NH,  g_Wih_h, g_Wih_l, 3*NHH, NHH, col0,
                      hbi, nullptr, g_IHI, g_psA + bid, 96, sm);
                gemmM(g_hAh, g_hAl, NHH, g_Whh_h, g_Whh_l, 3*NHH, NHH, col0,
                      hbh, nullptr, g_HHG, g_psB + bid, 96, sm);
            }
            gridbar();

            // ---- high combine -> h_h (+history at c==2) ----------------------
            if (w < 6) {
                const float2* p = (w < 3)
                    ? g_psA + (size_t)w*64*96 + b*96
                    : g_psB + (size_t)(w-3)*64*96 + b*96;
                float2 mr = warp_stat(p, 96, 1.f/NHH);
                if ((tid & 31) == 0) { s_st[2*w] = mr.x; s_st[2*w+1] = mr.y; }
            }
            __syncthreads();
            if (tid < 384) {
                const float* Ib = g_IHI + (size_t)b*3*NHH;
                const float* Hb = g_HHG + (size_t)b*3*NHH;
                int j = half*384 + tid;
                float i0 = (Ib[j        ] - s_st[0])*s_st[1]*hlig[j        ] + hlib[j        ];
                float i1 = (Ib[NHH  + j ] - s_st[2])*s_st[3]*hlig[NHH  + j ] + hlib[NHH  + j ];
                float i2 = (Ib[2*NHH + j] - s_st[4])*s_st[5]*hlig[2*NHH + j] + hlib[2*NHH + j];
                float h0 = (Hb[j        ] - s_st[6])*s_st[7]*hlhg[j        ] + hlhb[j        ];
                float h1 = (Hb[NHH  + j ] - s_st[8])*s_st[9]*hlhg[NHH  + j ] + hlhb[NHH  + j ];
                float h2 = (Hb[2*NHH + j] - s_st[10])*s_st[11]*hlhg[2*NHH + j] + hlhb[2*NHH + j];
                float r = sigm(i0 + h0);
                float z = sigm(i1 + h1);
                float n = tanhf(i2 + r*h2);
                float hp = g_hhT[(size_t)j*64 + b];
                float nv = (1.f - z)*n + z*hp;
                g_hhT[(size_t)j*64 + b] = nv;
                bf16 hh16 = __float2bfloat16(nv);
                g_hAh[(size_t)j*64 + b] = hh16;
                g_hAl[(size_t)j*64 + b] = __float2bfloat16(nv - __bfloat162float(hh16));
                if (c == 2) g_HH[(size_t)(t*64 + b)*NHH + j] = nv;
            }
            gridbar();
        }
    }
}

// ---------------- host orchestration ------------------------------------------
extern "C" void kernel_launch(void* const* d_in, const int* in_sizes, int n_in,
                              void* d_out, int out_size) {
    const int*   ids  = (const int*)  d_in[0];
    const float* emb  = (const float*)d_in[1];
    const float* leg  = (const float*)d_in[2];
    const float* leb  = (const float*)d_in[3];
    const float* lWi  = (const float*)d_in[4];   // [1536, 3072]
    const float* lbi  = (const float*)d_in[5];
    const float* lWh  = (const float*)d_in[6];   // [1024, 3072]
    const float* lbh  = (const float*)d_in[7];
    const float* llig = (const float*)d_in[8];
    const float* llib = (const float*)d_in[9];
    const float* llhg = (const float*)d_in[10];
    const float* llhb = (const float*)d_in[11];
    const float* hWi  = (const float*)d_in[12];  // [1024, 2304]
    const float* hbi  = (const float*)d_in[13];
    const float* hWh  = (const float*)d_in[14];  // [768, 2304]
    const float* hbh  = (const float*)d_in[15];
    const float* hlig = (const float*)d_in[16];
    const float* hlib = (const float*)d_in[17];
    const float* hlhg = (const float*)d_in[18];
    const float* hlhb = (const float*)d_in[19];
    const float* Wout = (const float*)d_in[20];  // [768, 32000]
    const float* bout = (const float*)d_in[21];
    float* out = (float*)d_out;

    float *pX, *pIX, *pHH;
    cudaGetSymbolAddress((void**)&pX,  g_X);
    cudaGetSymbolAddress((void**)&pIX, g_IX);
    cudaGetSymbolAddress((void**)&pHH, g_HH);
    bf16 *pWlh_h, *pWlh_l, *pWlx_h, *pWlx_l, *pWih_h, *pWih_l, *pWhh_h, *pWhh_l;
    cudaGetSymbolAddress((void**)&pWlh_h, g_Wlh_h);
    cudaGetSymbolAddress((void**)&pWlh_l, g_Wlh_l);
    cudaGetSymbolAddress((void**)&pWlx_h, g_Wlx_h);
    cudaGetSymbolAddress((void**)&pWlx_l, g_Wlx_l);
    cudaGetSymbolAddress((void**)&pWih_h, g_Wih_h);
    cudaGetSymbolAddress((void**)&pWih_l, g_Wih_l);
    cudaGetSymbolAddress((void**)&pWhh_h, g_Whh_h);
    cudaGetSymbolAddress((void**)&pWhh_l, g_Whh_l);

    // zero states + images
    k_init<<<256, 256>>>();

    // split weights into bf16 hi/lo
    {
        int n1 = NH*3*NH;    k_cvt<<<(n1 + 511)/512, 512>>>(lWh, pWlh_h, pWlh_l, n1);
        int n2 = NHH*3*NH;   k_cvt<<<(n2 + 511)/512, 512>>>(lWi + (size_t)NE*3*NH, pWlx_h, pWlx_l, n2);
        int n3 = NH*3*NHH;   k_cvt<<<(n3 + 511)/512, 512>>>(hWi, pWih_h, pWih_l, n3);
        int n4 = NHH*3*NHH;  k_cvt<<<(n4 + 511)/512, 512>>>(hWh, pWhh_h, pWhh_l, n4);
    }

    // x = LN(emb[ids]) laid out [S, B, E]
    k_embed<<<NB*NS, 256>>>(ids, emb, leg, leb);

    // IX = x @ Wi_x + bi for ALL tokens up front (reused 15x per step)
    k_gemm_big<<<dim3((3*NH)/128, (NB*NS)/128), 256>>>(pX, lWi, lbi, pIX, NE, 3*NH, 0);

    // full recurrence in ONE persistent kernel (tensor-core GEMMs)
    k_recur<<<GRID, TPB>>>(lbh,
                           llig, llib, llhg, llhb,
                           hbi, hbh,
                           hlig, hlib, hlhg, hlhb);

    // logits = h_h_hist @ Wout + bout, row remap (s*64+b) -> out[(b*64+s)*V]
    k_gemm_big<<<dim3(NV/128, (NB*NS)/128), 256>>>(pHH, Wout, bout, out, NHH, NV, 1);
}